// round 1
// baseline (speedup 1.0000x reference)
#include <cuda_runtime.h>
#include <math.h>

#define N_NODES 100000
#define N_HID   256
#define N_EDGES 3200000

// ---- scratch in device globals (no allocation allowed) ----
__device__ int   g_out_deg[N_NODES];
__device__ int   g_in_deg[N_NODES];
__device__ float g_h1s[N_NODES];
__device__ float g_agg[N_NODES];
__device__ float g_W1[N_HID];      // W[:,1]
__device__ float g_pe_s[N_HID];    // pe_coff * pe(t+1)
__device__ float g_pe_dot;         // dot(pe_s, W1)
__device__ float g_b1;

// K0: zero scratch + compute PE row, W1, pe_dot, b1
__global__ void k_init(const float* __restrict__ W,
                       const float* __restrict__ b,
                       const float* __restrict__ pe_coff,
                       const int*   __restrict__ t_ptr) {
    int i = blockIdx.x * blockDim.x + threadIdx.x;
    int stride = gridDim.x * blockDim.x;
    for (int j = i; j < N_NODES; j += stride) {
        g_out_deg[j] = 0;
        g_in_deg[j]  = 0;
        g_agg[j]     = 0.0f;
    }
    if (blockIdx.x == 0) {
        int c = threadIdx.x;               // 256 threads == N_HID
        float w1 = W[c * 2 + 1];
        g_W1[c] = w1;
        int t = *t_ptr;                    // works for int32 or little-endian int64 (small t)
        float pos  = (float)(t + 1);
        float coff = pe_coff[0];
        int even = c & ~1;
        float div = expf((float)even * (-logf(10000.0f) / (float)N_HID));
        float pe  = (c & 1) ? cosf(pos * div) : sinf(pos * div);
        float pes = coff * pe;
        g_pe_s[c] = pes;
        __shared__ float sred[256];
        sred[c] = pes * w1;
        __syncthreads();
        for (int s = 128; s > 0; s >>= 1) {
            if (c < s) sred[c] += sred[c + s];
            __syncthreads();
        }
        if (c == 0) {
            g_pe_dot = sred[0];
            g_b1 = b[1];
        }
    }
}

// K1: degree counting (4 edges per thread)
__global__ void k_deg(const int* __restrict__ src, const int* __restrict__ dst) {
    int i = blockIdx.x * blockDim.x + threadIdx.x;
    const int n4 = N_EDGES / 4;
    if (i >= n4) return;
    int4 s = ((const int4*)src)[i];
    int4 d = ((const int4*)dst)[i];
    atomicAdd(&g_out_deg[s.x], 1);
    atomicAdd(&g_out_deg[s.y], 1);
    atomicAdd(&g_out_deg[s.z], 1);
    atomicAdd(&g_out_deg[s.w], 1);
    atomicAdd(&g_in_deg[d.x], 1);
    atomicAdd(&g_in_deg[d.y], 1);
    atomicAdd(&g_in_deg[d.z], 1);
    atomicAdd(&g_in_deg[d.w], 1);
}

// K2: warp-per-row dot(input[r], W1), normalized by out-degree
__global__ void k_h1(const float* __restrict__ input) {
    int warp = (blockIdx.x * blockDim.x + threadIdx.x) >> 5;
    int lane = threadIdx.x & 31;
    if (warp >= N_NODES) return;
    const float4* row = (const float4*)(input + (size_t)warp * N_HID);
    const float4* w4  = (const float4*)g_W1;
    float acc = 0.0f;
#pragma unroll
    for (int k = 0; k < 2; k++) {
        int c4 = lane + k * 32;
        float4 v = row[c4];
        float4 w = w4[c4];
        acc += v.x * w.x + v.y * w.y + v.z * w.z + v.w * w.w;
    }
#pragma unroll
    for (int o = 16; o > 0; o >>= 1)
        acc += __shfl_xor_sync(0xffffffffu, acc, o);
    if (lane == 0) {
        float od = (float)max(g_out_deg[warp], 1);
        g_h1s[warp] = (acc + g_pe_dot) * rsqrtf(od);
    }
}

// K3: edge aggregation into agg[dst]
__global__ void k_agg(const int* __restrict__ src, const int* __restrict__ dst) {
    int i = blockIdx.x * blockDim.x + threadIdx.x;
    const int n4 = N_EDGES / 4;
    if (i >= n4) return;
    int4 s = ((const int4*)src)[i];
    int4 d = ((const int4*)dst)[i];
    atomicAdd(&g_agg[d.x], __ldg(&g_h1s[s.x]));
    atomicAdd(&g_agg[d.y], __ldg(&g_h1s[s.y]));
    atomicAdd(&g_agg[d.z], __ldg(&g_h1s[s.z]));
    atomicAdd(&g_agg[d.w], __ldg(&g_h1s[s.w]));
}

// K4: out[r][c] = (input[r][c] + pe_s[c]) * sigmoid(relu(agg[r]*rsqrt(in_deg)+b1))
__global__ void k_out(const float* __restrict__ input, float* __restrict__ out) {
    long long idx = (long long)blockIdx.x * blockDim.x + threadIdx.x;
    const long long total = (long long)N_NODES * (N_HID / 4);
    if (idx >= total) return;
    int row = (int)(idx >> 6);   // N_HID/4 == 64
    int c4  = (int)(idx & 63);
    float z = g_agg[row] * rsqrtf((float)max(g_in_deg[row], 1)) + g_b1;
    z = fmaxf(z, 0.0f);
    float gate = 1.0f / (1.0f + expf(-z));
    float4 v = ((const float4*)input)[idx];
    float4 p = ((const float4*)g_pe_s)[c4];
    float4 o;
    o.x = (v.x + p.x) * gate;
    o.y = (v.y + p.y) * gate;
    o.z = (v.z + p.z) * gate;
    o.w = (v.w + p.w) * gate;
    ((float4*)out)[idx] = o;
}

extern "C" void kernel_launch(void* const* d_in, const int* in_sizes, int n_in,
                              void* d_out, int out_size) {
    const float* input   = (const float*)d_in[0];
    const float* W       = (const float*)d_in[1];
    const float* b       = (const float*)d_in[2];
    const float* pe_coff = (const float*)d_in[3];
    const int*   src     = (const int*)d_in[4];
    const int*   dst     = (const int*)d_in[5];
    const int*   t_ptr   = (const int*)d_in[6];
    float* out = (float*)d_out;

    // K0: init (block 0 must have exactly 256 threads for the PE row)
    k_init<<<256, 256>>>(W, b, pe_coff, t_ptr);

    // K1: degrees — N_EDGES/4 threads
    {
        int n4 = N_EDGES / 4;
        k_deg<<<(n4 + 255) / 256, 256>>>(src, dst);
    }

    // K2: per-node dot — warp per row, 8 warps / block
    {
        int nwarps = N_NODES;
        int blocks = (nwarps + 7) / 8;
        k_h1<<<blocks, 256>>>(input);
    }

    // K3: aggregate
    {
        int n4 = N_EDGES / 4;
        k_agg<<<(n4 + 255) / 256, 256>>>(src, dst);
    }

    // K4: gated output — float4 per thread
    {
        long long total = (long long)N_NODES * (N_HID / 4);
        int blocks = (int)((total + 255) / 256);
        k_out<<<blocks, 256>>>(input, out);
    }
}

// round 2
// speedup vs baseline: 1.2701x; 1.2701x over previous
#include <cuda_runtime.h>
#include <math.h>

#define N_NODES 100000
#define N_HID   256
#define N_EDGES 3200000

// ---- scratch in device globals (no allocation allowed) ----
__device__ int    g_out_deg[N_NODES];
__device__ float  g_hun[N_NODES];                       // unscaled dot
__device__ float  g_h1s[N_NODES];                       // scaled
__device__ __align__(8) float2 g_aggcnt[N_NODES];       // {agg_sum, in_deg_count}
__device__ float  g_W1[N_HID];                          // W[:,1]
__device__ float  g_pe_s[N_HID];                        // pe_coff * pe(t+1)
__device__ float  g_pe_dot;
__device__ float  g_b1;

// K0: zero scratch + compute PE row, W1, pe_dot, b1
__global__ void k_init(const float* __restrict__ W,
                       const float* __restrict__ b,
                       const float* __restrict__ pe_coff,
                       const int*   __restrict__ t_ptr) {
    int i = blockIdx.x * blockDim.x + threadIdx.x;
    int stride = gridDim.x * blockDim.x;
    for (int j = i; j < N_NODES; j += stride) {
        g_out_deg[j] = 0;
        g_aggcnt[j]  = make_float2(0.0f, 0.0f);
    }
    if (blockIdx.x == 0) {
        int c = threadIdx.x;               // 256 threads == N_HID
        float w1 = W[c * 2 + 1];
        g_W1[c] = w1;
        int t = *t_ptr;
        float pos  = (float)(t + 1);
        float coff = pe_coff[0];
        int even = c & ~1;
        float div = expf((float)even * (-logf(10000.0f) / (float)N_HID));
        float pe  = (c & 1) ? cosf(pos * div) : sinf(pos * div);
        float pes = coff * pe;
        g_pe_s[c] = pes;
        __shared__ float sred[256];
        sred[c] = pes * w1;
        __syncthreads();
        for (int s = 128; s > 0; s >>= 1) {
            if (c < s) sred[c] += sred[c + s];
            __syncthreads();
        }
        if (c == 0) {
            g_pe_dot = sred[0];
            g_b1 = b[1];
        }
    }
}

// K1 fused: interleaved block roles.
//   blockIdx.x % 5 == 0  -> edge block: out-degree atomics (src only)
//   otherwise            -> node block: warp-per-row unscaled dot(input[r], W1)
// Edge blocks: 3125 (N_EDGES/4/256). Node blocks: 12500 (8 rows each).
#define FUSED_GRID 15625
__global__ void k_fused(const float* __restrict__ input,
                        const int*   __restrict__ src) {
    int b = blockIdx.x;
    if (b % 5 == 0) {
        // ---- edge role: out-degree ----
        int eb = b / 5;
        int i = eb * 256 + threadIdx.x;
        if (i < N_EDGES / 4) {
            int4 s = ((const int4*)src)[i];
            atomicAdd(&g_out_deg[s.x], 1);
            atomicAdd(&g_out_deg[s.y], 1);
            atomicAdd(&g_out_deg[s.z], 1);
            atomicAdd(&g_out_deg[s.w], 1);
        }
    } else {
        // ---- node role: dot product ----
        int nb = b - (b / 5 + 1);            // 0..12499
        int warp_in_block = threadIdx.x >> 5;
        int lane = threadIdx.x & 31;
        int row = nb * 8 + warp_in_block;
        if (row < N_NODES) {
            const float4* rowp = (const float4*)(input + (size_t)row * N_HID);
            const float4* w4   = (const float4*)g_W1;
            float acc = 0.0f;
#pragma unroll
            for (int k = 0; k < 2; k++) {
                int c4 = lane + k * 32;
                float4 v = rowp[c4];
                float4 w = w4[c4];
                acc += v.x * w.x + v.y * w.y + v.z * w.z + v.w * w.w;
            }
#pragma unroll
            for (int o = 16; o > 0; o >>= 1)
                acc += __shfl_xor_sync(0xffffffffu, acc, o);
            if (lane == 0) g_hun[row] = acc;
        }
    }
}

// K2: scale by out-degree norm (tiny)
__global__ void k_scale() {
    int i = blockIdx.x * blockDim.x + threadIdx.x;
    if (i >= N_NODES) return;
    float od = (float)max(g_out_deg[i], 1);
    g_h1s[i] = (g_hun[i] + g_pe_dot) * rsqrtf(od);
}

// K3: edge aggregation — ONE v2 float reduction per edge: {h, 1.0} -> {agg, cnt}
__global__ void k_agg(const int* __restrict__ src, const int* __restrict__ dst) {
    int i = blockIdx.x * blockDim.x + threadIdx.x;
    const int n4 = N_EDGES / 4;
    if (i >= n4) return;
    int4 s = ((const int4*)src)[i];
    int4 d = ((const int4*)dst)[i];
    float h0 = __ldg(&g_h1s[s.x]);
    float h1 = __ldg(&g_h1s[s.y]);
    float h2 = __ldg(&g_h1s[s.z]);
    float h3 = __ldg(&g_h1s[s.w]);
    const float one = 1.0f;
    asm volatile("red.global.add.v2.f32 [%0], {%1, %2};"
                 :: "l"(&g_aggcnt[d.x]), "f"(h0), "f"(one) : "memory");
    asm volatile("red.global.add.v2.f32 [%0], {%1, %2};"
                 :: "l"(&g_aggcnt[d.y]), "f"(h1), "f"(one) : "memory");
    asm volatile("red.global.add.v2.f32 [%0], {%1, %2};"
                 :: "l"(&g_aggcnt[d.z]), "f"(h2), "f"(one) : "memory");
    asm volatile("red.global.add.v2.f32 [%0], {%1, %2};"
                 :: "l"(&g_aggcnt[d.w]), "f"(h3), "f"(one) : "memory");
}

// K4: out[r][c] = (input[r][c] + pe_s[c]) * sigmoid(relu(agg/sqrt(max(cnt,1)) + b1))
__global__ void k_out(const float* __restrict__ input, float* __restrict__ out) {
    long long idx = (long long)blockIdx.x * blockDim.x + threadIdx.x;
    const long long total = (long long)N_NODES * (N_HID / 4);
    if (idx >= total) return;
    int row = (int)(idx >> 6);   // N_HID/4 == 64
    int c4  = (int)(idx & 63);
    float2 ac = g_aggcnt[row];
    float z = ac.x * rsqrtf(fmaxf(ac.y, 1.0f)) + g_b1;
    z = fmaxf(z, 0.0f);
    float gate = 1.0f / (1.0f + expf(-z));
    float4 v = ((const float4*)input)[idx];
    float4 p = ((const float4*)g_pe_s)[c4];
    float4 o;
    o.x = (v.x + p.x) * gate;
    o.y = (v.y + p.y) * gate;
    o.z = (v.z + p.z) * gate;
    o.w = (v.w + p.w) * gate;
    ((float4*)out)[idx] = o;
}

extern "C" void kernel_launch(void* const* d_in, const int* in_sizes, int n_in,
                              void* d_out, int out_size) {
    const float* input   = (const float*)d_in[0];
    const float* W       = (const float*)d_in[1];
    const float* b       = (const float*)d_in[2];
    const float* pe_coff = (const float*)d_in[3];
    const int*   src     = (const int*)d_in[4];
    const int*   dst     = (const int*)d_in[5];
    const int*   t_ptr   = (const int*)d_in[6];
    float* out = (float*)d_out;

    k_init<<<256, 256>>>(W, b, pe_coff, t_ptr);

    k_fused<<<FUSED_GRID, 256>>>(input, src);

    k_scale<<<(N_NODES + 255) / 256, 256>>>();

    {
        int n4 = N_EDGES / 4;
        k_agg<<<(n4 + 255) / 256, 256>>>(src, dst);
    }

    {
        long long total = (long long)N_NODES * (N_HID / 4);
        int blocks = (int)((total + 255) / 256);
        k_out<<<blocks, 256>>>(input, out);
    }
}

// round 3
// speedup vs baseline: 1.3914x; 1.0955x over previous
#include <cuda_runtime.h>
#include <math.h>

#define N_NODES 100000
#define N_HID   256
#define N_EDGES 3200000

// ---- scratch in device globals (no allocation allowed) ----
__device__ int    g_out_deg[N_NODES];
__device__ float  g_hun[N_NODES];                       // unscaled dot
__device__ float  g_h1s[N_NODES];                       // scaled
__device__ __align__(8) float2 g_aggcnt[N_NODES];       // {agg_sum, in_deg_count}
__device__ float  g_W1[N_HID];                          // W[:,1]
__device__ float  g_pe_s[N_HID];                        // pe_coff * pe(t+1)
__device__ float  g_pe_dot;
__device__ float  g_b1;

// K0: zero scratch + compute PE row, W1, pe_dot, b1
__global__ void k_init(const float* __restrict__ W,
                       const float* __restrict__ b,
                       const float* __restrict__ pe_coff,
                       const int*   __restrict__ t_ptr) {
    int i = blockIdx.x * blockDim.x + threadIdx.x;
    int stride = gridDim.x * blockDim.x;
    for (int j = i; j < N_NODES; j += stride) {
        g_out_deg[j] = 0;
        g_aggcnt[j]  = make_float2(0.0f, 0.0f);
    }
    if (blockIdx.x == 0) {
        int c = threadIdx.x;               // 256 threads == N_HID
        float w1 = W[c * 2 + 1];
        g_W1[c] = w1;
        int t = *t_ptr;
        float pos  = (float)(t + 1);
        float coff = pe_coff[0];
        int even = c & ~1;
        float div = expf((float)even * (-logf(10000.0f) / (float)N_HID));
        float pe  = (c & 1) ? cosf(pos * div) : sinf(pos * div);
        float pes = coff * pe;
        g_pe_s[c] = pes;
        __shared__ float sred[256];
        sred[c] = pes * w1;
        __syncthreads();
        for (int s = 128; s > 0; s >>= 1) {
            if (c < s) sred[c] += sred[c + s];
            __syncthreads();
        }
        if (c == 0) {
            g_pe_dot = sred[0];
            g_b1 = b[1];
        }
    }
}

// K1 fused: interleaved block roles (1 edge block per 4 node blocks).
// PDL secondary of k_init: prologue loads pure inputs, then grid-dep sync.
#define FUSED_GRID 15625
__global__ void k_fused(const float* __restrict__ input,
                        const int*   __restrict__ src) {
    int b = blockIdx.x;
    if (b % 5 == 0) {
        // ---- edge role: out-degree atomics ----
        int eb = b / 5;
        int i = eb * 256 + threadIdx.x;
        int4 s = make_int4(0, 0, 0, 0);
        bool act = (i < N_EDGES / 4);
        if (act) s = __ldcs(&((const int4*)src)[i]);   // streaming: don't pollute L2
        cudaGridDependencySynchronize();               // wait k_init (zeroed counters)
        if (act) {
            atomicAdd(&g_out_deg[s.x], 1);
            atomicAdd(&g_out_deg[s.y], 1);
            atomicAdd(&g_out_deg[s.z], 1);
            atomicAdd(&g_out_deg[s.w], 1);
        }
    } else {
        // ---- node role: unscaled dot(input[r], W1) ----
        int nb = b - (b / 5 + 1);            // 0..12499
        int warp_in_block = threadIdx.x >> 5;
        int lane = threadIdx.x & 31;
        int row = nb * 8 + warp_in_block;
        float4 v0 = make_float4(0, 0, 0, 0), v1 = v0;
        bool act = (row < N_NODES);
        if (act) {
            const float4* rowp = (const float4*)(input + (size_t)row * N_HID);
            v0 = rowp[lane];          // default policy: keep resident in L2 for k_out
            v1 = rowp[lane + 32];
        }
        cudaGridDependencySynchronize();               // g_W1 written by k_init
        if (act) {
            const float4* w4 = (const float4*)g_W1;
            float4 w0 = w4[lane];
            float4 w1 = w4[lane + 32];
            float acc = v0.x * w0.x + v0.y * w0.y + v0.z * w0.z + v0.w * w0.w
                      + v1.x * w1.x + v1.y * w1.y + v1.z * w1.z + v1.w * w1.w;
#pragma unroll
            for (int o = 16; o > 0; o >>= 1)
                acc += __shfl_xor_sync(0xffffffffu, acc, o);
            if (lane == 0) g_hun[row] = acc;
        }
    }
}

// K2: scale by out-degree norm (tiny)
__global__ void k_scale() {
    int i = blockIdx.x * blockDim.x + threadIdx.x;
    cudaGridDependencySynchronize();
    if (i >= N_NODES) return;
    float od = (float)max(g_out_deg[i], 1);
    g_h1s[i] = (g_hun[i] + g_pe_dot) * rsqrtf(od);
}

// K3: edge aggregation — one v2 red per edge: {h, 1.0} -> {agg, cnt}. 8 edges/thread.
__global__ void k_agg(const int* __restrict__ src, const int* __restrict__ dst) {
    int i = blockIdx.x * blockDim.x + threadIdx.x;
    const int n8 = N_EDGES / 8;
    int4 s0 = make_int4(0,0,0,0), s1 = s0, d0 = s0, d1 = s0;
    bool act = (i < n8);
    if (act) {
        s0 = __ldcs(&((const int4*)src)[2 * i]);
        s1 = __ldcs(&((const int4*)src)[2 * i + 1]);
        d0 = __ldcs(&((const int4*)dst)[2 * i]);
        d1 = __ldcs(&((const int4*)dst)[2 * i + 1]);
    }
    cudaGridDependencySynchronize();                   // h1s ready (k_scale done)
    if (!act) return;
    float h0 = __ldg(&g_h1s[s0.x]);
    float h1 = __ldg(&g_h1s[s0.y]);
    float h2 = __ldg(&g_h1s[s0.z]);
    float h3 = __ldg(&g_h1s[s0.w]);
    float h4 = __ldg(&g_h1s[s1.x]);
    float h5 = __ldg(&g_h1s[s1.y]);
    float h6 = __ldg(&g_h1s[s1.z]);
    float h7 = __ldg(&g_h1s[s1.w]);
    const float one = 1.0f;
#define REDV2(p, h) asm volatile("red.global.add.v2.f32 [%0], {%1, %2};" :: "l"(p), "f"(h), "f"(one) : "memory")
    REDV2(&g_aggcnt[d0.x], h0);
    REDV2(&g_aggcnt[d0.y], h1);
    REDV2(&g_aggcnt[d0.z], h2);
    REDV2(&g_aggcnt[d0.w], h3);
    REDV2(&g_aggcnt[d1.x], h4);
    REDV2(&g_aggcnt[d1.y], h5);
    REDV2(&g_aggcnt[d1.z], h6);
    REDV2(&g_aggcnt[d1.w], h7);
#undef REDV2
}

// K4: out[r][c] = (input[r][c] + pe_s[c]) * sigmoid(relu(agg/sqrt(max(cnt,1)) + b1))
__global__ void k_out(const float* __restrict__ input, float* __restrict__ out) {
    long long idx = (long long)blockIdx.x * blockDim.x + threadIdx.x;
    const long long total = (long long)N_NODES * (N_HID / 4);
    bool act = (idx < total);
    float4 v = make_float4(0, 0, 0, 0);
    if (act) v = ((const float4*)input)[idx];          // overlap with k_agg tail (L2 hit)
    cudaGridDependencySynchronize();                   // aggcnt final
    if (!act) return;
    int row = (int)(idx >> 6);   // N_HID/4 == 64
    int c4  = (int)(idx & 63);
    float2 ac = g_aggcnt[row];
    float z = ac.x * rsqrtf(fmaxf(ac.y, 1.0f)) + g_b1;
    z = fmaxf(z, 0.0f);
    float gate = 1.0f / (1.0f + expf(-z));
    float4 p = ((const float4*)g_pe_s)[c4];
    float4 o;
    o.x = (v.x + p.x) * gate;
    o.y = (v.y + p.y) * gate;
    o.z = (v.z + p.z) * gate;
    o.w = (v.w + p.w) * gate;
    __stcs(&((float4*)out)[idx], o);                   // evict-first: keep input in L2
}

template <typename K, typename... Args>
static inline void launch_pdl(K kern, int grid, int block, Args... args) {
    cudaLaunchConfig_t cfg = {};
    cfg.gridDim = dim3(grid, 1, 1);
    cfg.blockDim = dim3(block, 1, 1);
    cfg.dynamicSmemBytes = 0;
    cfg.stream = 0;
    cudaLaunchAttribute attr[1];
    attr[0].id = cudaLaunchAttributeProgrammaticStreamSerialization;
    attr[0].val.programmaticStreamSerializationAllowed = 1;
    cfg.attrs = attr;
    cfg.numAttrs = 1;
    cudaLaunchKernelEx(&cfg, kern, args...);
}

extern "C" void kernel_launch(void* const* d_in, const int* in_sizes, int n_in,
                              void* d_out, int out_size) {
    const float* input   = (const float*)d_in[0];
    const float* W       = (const float*)d_in[1];
    const float* b       = (const float*)d_in[2];
    const float* pe_coff = (const float*)d_in[3];
    const int*   src     = (const int*)d_in[4];
    const int*   dst     = (const int*)d_in[5];
    const int*   t_ptr   = (const int*)d_in[6];
    float* out = (float*)d_out;

    k_init<<<256, 256>>>(W, b, pe_coff, t_ptr);

    launch_pdl(k_fused, FUSED_GRID, 256, input, src);

    launch_pdl(k_scale, (N_NODES + 255) / 256, 256);

    {
        int n8 = N_EDGES / 8;
        launch_pdl(k_agg, (n8 + 255) / 256, 256, src, dst);
    }

    {
        long long total = (long long)N_NODES * (N_HID / 4);
        int blocks = (int)((total + 255) / 256);
        launch_pdl(k_out, blocks, 256, input, out);
    }
}

// round 4
// speedup vs baseline: 1.4386x; 1.0339x over previous
#include <cuda_runtime.h>
#include <cuda_fp16.h>
#include <math.h>

#define N_NODES 100000
#define N_HID   256
#define N_EDGES 3200000

// ---- scratch in device globals (no allocation allowed) ----
__device__ int    g_out_deg[N_NODES];
__device__ float  g_hun[N_NODES];                       // unscaled dot
__device__ __half g_h1h[N_NODES];                       // scaled, fp16 (gather table)
__device__ __align__(8) float2 g_aggcnt[N_NODES];       // {agg_sum, in_deg_count}
__device__ float  g_W1[N_HID];                          // W[:,1]
__device__ float  g_pe_s[N_HID];                        // pe_coff * pe(t+1)
__device__ float  g_pe_dot;
__device__ float  g_b1;

// K0: zero scratch + compute PE row, W1, pe_dot, b1
__global__ void k_init(const float* __restrict__ W,
                       const float* __restrict__ b,
                       const float* __restrict__ pe_coff,
                       const int*   __restrict__ t_ptr) {
    int i = blockIdx.x * blockDim.x + threadIdx.x;
    int stride = gridDim.x * blockDim.x;
    for (int j = i; j < N_NODES; j += stride) {
        g_out_deg[j] = 0;
        g_aggcnt[j]  = make_float2(0.0f, 0.0f);
    }
    if (blockIdx.x == 0) {
        int c = threadIdx.x;               // 256 threads == N_HID
        float w1 = W[c * 2 + 1];
        g_W1[c] = w1;
        int t = *t_ptr;
        float pos  = (float)(t + 1);
        float coff = pe_coff[0];
        int even = c & ~1;
        float div = expf((float)even * (-logf(10000.0f) / (float)N_HID));
        float pe  = (c & 1) ? cosf(pos * div) : sinf(pos * div);
        float pes = coff * pe;
        g_pe_s[c] = pes;
        __shared__ float sred[256];
        sred[c] = pes * w1;
        __syncthreads();
        for (int s = 128; s > 0; s >>= 1) {
            if (c < s) sred[c] += sred[c + s];
            __syncthreads();
        }
        if (c == 0) {
            g_pe_dot = sred[0];
            g_b1 = b[1];
        }
    }
}

// K1 fused: interleaved block roles (1 edge block per 4 node blocks).
#define FUSED_GRID 15625
__global__ void k_fused(const float* __restrict__ input,
                        const int*   __restrict__ src) {
    int b = blockIdx.x;
    if (b % 5 == 0) {
        // ---- edge role: out-degree atomics ----
        int eb = b / 5;
        int i = eb * 256 + threadIdx.x;
        int4 s = make_int4(0, 0, 0, 0);
        bool act = (i < N_EDGES / 4);
        if (act) s = __ldcs(&((const int4*)src)[i]);   // streaming: don't pollute L2
        cudaGridDependencySynchronize();               // wait k_init (zeroed counters)
        if (act) {
            atomicAdd(&g_out_deg[s.x], 1);
            atomicAdd(&g_out_deg[s.y], 1);
            atomicAdd(&g_out_deg[s.z], 1);
            atomicAdd(&g_out_deg[s.w], 1);
        }
    } else {
        // ---- node role: unscaled dot(input[r], W1) ----
        int nb = b - (b / 5 + 1);            // 0..12499
        int warp_in_block = threadIdx.x >> 5;
        int lane = threadIdx.x & 31;
        int row = nb * 8 + warp_in_block;
        float4 v0 = make_float4(0, 0, 0, 0), v1 = v0;
        bool act = (row < N_NODES);
        if (act) {
            const float4* rowp = (const float4*)(input + (size_t)row * N_HID);
            v0 = rowp[lane];          // default policy: stays L2-resident for k_out
            v1 = rowp[lane + 32];
        }
        cudaGridDependencySynchronize();               // g_W1 written by k_init
        if (act) {
            const float4* w4 = (const float4*)g_W1;
            float4 w0 = w4[lane];
            float4 w1 = w4[lane + 32];
            float acc = v0.x * w0.x + v0.y * w0.y + v0.z * w0.z + v0.w * w0.w
                      + v1.x * w1.x + v1.y * w1.y + v1.z * w1.z + v1.w * w1.w;
#pragma unroll
            for (int o = 16; o > 0; o >>= 1)
                acc += __shfl_xor_sync(0xffffffffu, acc, o);
            if (lane == 0) g_hun[row] = acc;
        }
    }
}

// K2: scale by out-degree norm, store fp16 gather table (tiny)
__global__ void k_scale() {
    int i = blockIdx.x * blockDim.x + threadIdx.x;
    cudaGridDependencySynchronize();
    if (i >= N_NODES) return;
    float od = (float)max(g_out_deg[i], 1);
    g_h1h[i] = __float2half((g_hun[i] + g_pe_dot) * rsqrtf(od));
}

// K3: persistent edge aggregation. The full fp16 h table lives in SMEM:
//   gathers become LDS (2x LDG issue rate, zero L2 ops), only RED + edge
//   loads stay on the LDG pipe -> 1.5 LDG-class ops/edge instead of 2.5.
__global__ void __launch_bounds__(1024, 1)
k_agg(const int* __restrict__ src, const int* __restrict__ dst) {
    extern __shared__ __half sh[];   // N_NODES halves = 200000 bytes
    int tid = blockIdx.x * blockDim.x + threadIdx.x;
    int nth = gridDim.x * blockDim.x;
    cudaGridDependencySynchronize();                   // h table ready (k_scale)
    // cooperative table load: 12500 uint4 (= 100000 halves) per block
    for (int j = threadIdx.x; j < N_NODES / 8; j += blockDim.x)
        ((uint4*)sh)[j] = ((const uint4*)g_h1h)[j];
    __syncthreads();
    const float one = 1.0f;
    const int n4 = N_EDGES / 4;
    for (int i = tid; i < n4; i += nth) {
        int4 s = __ldcs(&((const int4*)src)[i]);
        int4 d = __ldcs(&((const int4*)dst)[i]);
        float h0 = __half2float(sh[s.x]);
        float h1 = __half2float(sh[s.y]);
        float h2 = __half2float(sh[s.z]);
        float h3 = __half2float(sh[s.w]);
#define REDV2(p, h) asm volatile("red.global.add.v2.f32 [%0], {%1, %2};" :: "l"(p), "f"(h), "f"(one) : "memory")
        REDV2(&g_aggcnt[d.x], h0);
        REDV2(&g_aggcnt[d.y], h1);
        REDV2(&g_aggcnt[d.z], h2);
        REDV2(&g_aggcnt[d.w], h3);
#undef REDV2
    }
}

// K4: out[r][c] = (input[r][c] + pe_s[c]) * sigmoid(relu(agg/sqrt(max(cnt,1)) + b1))
__global__ void k_out(const float* __restrict__ input, float* __restrict__ out) {
    long long idx = (long long)blockIdx.x * blockDim.x + threadIdx.x;
    const long long total = (long long)N_NODES * (N_HID / 4);
    bool act = (idx < total);
    float4 v = make_float4(0, 0, 0, 0);
    if (act) v = ((const float4*)input)[idx];          // overlap with k_agg tail (L2 hit)
    cudaGridDependencySynchronize();                   // aggcnt final
    if (!act) return;
    int row = (int)(idx >> 6);   // N_HID/4 == 64
    int c4  = (int)(idx & 63);
    float2 ac = g_aggcnt[row];
    float z = ac.x * rsqrtf(fmaxf(ac.y, 1.0f)) + g_b1;
    z = fmaxf(z, 0.0f);
    float gate = 1.0f / (1.0f + expf(-z));
    float4 p = ((const float4*)g_pe_s)[c4];
    float4 o;
    o.x = (v.x + p.x) * gate;
    o.y = (v.y + p.y) * gate;
    o.z = (v.z + p.z) * gate;
    o.w = (v.w + p.w) * gate;
    __stcs(&((float4*)out)[idx], o);                   // evict-first: keep input in L2
}

template <typename K, typename... Args>
static inline void launch_pdl(K kern, int grid, int block, size_t smem, Args... args) {
    cudaLaunchConfig_t cfg = {};
    cfg.gridDim = dim3(grid, 1, 1);
    cfg.blockDim = dim3(block, 1, 1);
    cfg.dynamicSmemBytes = smem;
    cfg.stream = 0;
    cudaLaunchAttribute attr[1];
    attr[0].id = cudaLaunchAttributeProgrammaticStreamSerialization;
    attr[0].val.programmaticStreamSerializationAllowed = 1;
    cfg.attrs = attr;
    cfg.numAttrs = 1;
    cudaLaunchKernelEx(&cfg, kern, args...);
}

extern "C" void kernel_launch(void* const* d_in, const int* in_sizes, int n_in,
                              void* d_out, int out_size) {
    const float* input   = (const float*)d_in[0];
    const float* W       = (const float*)d_in[1];
    const float* b       = (const float*)d_in[2];
    const float* pe_coff = (const float*)d_in[3];
    const int*   src     = (const int*)d_in[4];
    const int*   dst     = (const int*)d_in[5];
    const int*   t_ptr   = (const int*)d_in[6];
    float* out = (float*)d_out;

    const size_t AGG_SMEM = (size_t)N_NODES * sizeof(__half);   // 200000 B
    cudaFuncSetAttribute(k_agg, cudaFuncAttributeMaxDynamicSharedMemorySize,
                         (int)AGG_SMEM);
    int n_sm = 148;
    cudaDeviceGetAttribute(&n_sm, cudaDevAttrMultiProcessorCount, 0);
    if (n_sm <= 0) n_sm = 148;

    k_init<<<256, 256>>>(W, b, pe_coff, t_ptr);

    launch_pdl(k_fused, FUSED_GRID, 256, 0, input, src);

    launch_pdl(k_scale, (N_NODES + 255) / 256, 256, 0);

    launch_pdl(k_agg, n_sm, 1024, AGG_SMEM, src, dst);

    {
        long long total = (long long)N_NODES * (N_HID / 4);
        int blocks = (int)((total + 255) / 256);
        launch_pdl(k_out, blocks, 256, 0, input, out);
    }
}